// round 13
// baseline (speedup 1.0000x reference)
#include <cuda_runtime.h>
#include <cuda_fp16.h>
#include <cstdint>

// ---------------------------------------------------------------------------
// FermiLayer: N=512 (256 up / 256 dn), SINGLE=256, PAIR=128
// inputs: [0] h_one (512,256) [1] h_two (512,512,128) [2] W1 (512,256)
//         [3] b1 (256) [4] Wg (512,256) [5] W2 (128,128) [6] b2 (128)
// output: [h_one_out | h_two_out] fp32
// k_two: single-pass fp16 mma.sync, 64x128 tiles, 128-thread CTAs,
// 4 CTAs/SM (4 overlapping stage/MMA/epilogue pipelines per SM).
// j-pair per block + L2 prefetch. g2 partials (8 x 64-row chunks) + gtp
// fused into k_two's grid.
// ---------------------------------------------------------------------------

#define GAIN    1.5927812698663017f
#define RSQRT2  0.7071067811865475f
#define INV256  0.00390625f

typedef unsigned long long u64;
typedef unsigned int u32;

// scratch (__device__ globals: allocation-free rule)
__device__ float g_g2p[8 * 512 * 128];   // [ch][j][p], ch = s*4+h, 64 rows each
__device__ float g_g1p[16 * 256];        // g1 partials
__device__ float g_gtp[16 * 256];        // gt partials (16 k-chunks)
__device__ __align__(16) unsigned char g_w2h[35840];  // W2^T fp16, stride 272B

__device__ __forceinline__ float tanh_fast(float x) {
    float y;
    asm("tanh.approx.f32 %0, %1;" : "=f"(y) : "f"(x));
    return y;
}
__device__ __forceinline__ u32 smem_u32(const void* p) {
    u32 a;
    asm("{ .reg .u64 t; cvta.to.shared.u64 t, %1; cvt.u32.u64 %0, t; }" : "=r"(a) : "l"(p));
    return a;
}
__device__ __forceinline__ void ldsm4(u32* r, u32 addr) {
    asm volatile("ldmatrix.sync.aligned.m8n8.x4.shared.b16 {%0,%1,%2,%3}, [%4];"
                 : "=r"(r[0]), "=r"(r[1]), "=r"(r[2]), "=r"(r[3]) : "r"(addr));
}
__device__ __forceinline__ void mma16816(float* c, const u32* a, const u32* b) {
    asm volatile(
        "mma.sync.aligned.m16n8k16.row.col.f32.f16.f16.f32 "
        "{%0,%1,%2,%3}, {%4,%5,%6,%7}, {%8,%9}, {%0,%1,%2,%3};"
        : "+f"(c[0]), "+f"(c[1]), "+f"(c[2]), "+f"(c[3])
        : "r"(a[0]), "r"(a[1]), "r"(a[2]), "r"(a[3]), "r"(b[0]), "r"(b[1]));
}
__device__ __forceinline__ void prefetch_l2(const void* p) {
    asm volatile("prefetch.global.L2 [%0];" :: "l"(p));
}

#define BSTRIDE 272
#define S_AH  0
#define S_WH  17408
#define S_RED 52224
#define SMEM_TWO 54272

// ---------------------------------------------------------------------------
// K0: merged prep. blocks 0..15: W2T fp16 image. blocks 16..31: g1 partials.
// ---------------------------------------------------------------------------
__global__ void k_prep(const float* __restrict__ W2,
                       const float* __restrict__ h_one) {
    int b = blockIdx.x;
    if (b < 16) {
        int t = b * 256 + threadIdx.x;
        int n = t >> 5;
        int k = (t & 31) * 4;
        __half2 h0 = __float22half2_rn(make_float2(W2[(k + 0) * 128 + n], W2[(k + 1) * 128 + n]));
        __half2 h1 = __float22half2_rn(make_float2(W2[(k + 2) * 128 + n], W2[(k + 3) * 128 + n]));
        u64 hp = (u64)(*(u32*)&h0) | ((u64)(*(u32*)&h1) << 32);
        *(u64*)(g_w2h + n * BSTRIDE + k * 2) = hp;
    } else {
        int bb = b - 16;
        int s = bb >> 3, ck = bb & 7;
        int c = threadIdx.x;
        const float* p = h_one + (size_t)(s * 256 + ck * 32) * 256 + c;
        float sum = 0.f;
#pragma unroll 8
        for (int r = 0; r < 32; r++) sum += p[r * 256];
        g_g1p[bb * 256 + c] = sum;
    }
}

// ---------------------------------------------------------------------------
// K2: h_one path. 128 blocks x 256 threads, 4 rows/block.
// Combines 4 g2 chunk-partials per spin + gt partials (+b1).
// ---------------------------------------------------------------------------
__global__ void __launch_bounds__(256)
k_one(const float* __restrict__ h_one,
      const float* __restrict__ W1,
      const float* __restrict__ b1,
      float* __restrict__ out_one) {
    __shared__ float s_in[2048];
    int tid = threadIdx.x;
    int r0 = blockIdx.x * 4;
#pragma unroll
    for (int i = 0; i < 8; i++) {
        int e = tid + i * 256;
        int k = e >> 2;
        int r = e & 3;
        int n = r0 + r;
        float v;
        if (k < 256) {
            v = h_one[n * 256 + k];
        } else {
            int sp = (k < 384) ? 0 : 1;
            int p = k - 256 - sp * 128;
            size_t base = (size_t)(sp * 4) * 65536 + (size_t)n * 128 + p;
            v = (g_g2p[base] + g_g2p[base + 65536] +
                 g_g2p[base + 131072] + g_g2p[base + 196608]) * INV256;
        }
        s_in[k * 4 + r] = v;
    }
    __syncthreads();

    int c = tid;
    float acc[4] = {0.f, 0.f, 0.f, 0.f};
#pragma unroll 4
    for (int kb = 0; kb < 64; kb++) {
        float w[8];
#pragma unroll
        for (int i = 0; i < 8; i++) w[i] = W1[(kb * 8 + i) * 256 + c];
#pragma unroll
        for (int i = 0; i < 8; i++) {
            float4 a = *(const float4*)(s_in + (kb * 8 + i) * 4);
            acc[0] += a.x * w[i];
            acc[1] += a.y * w[i];
            acc[2] += a.z * w[i];
            acc[3] += a.w * w[i];
        }
    }
    float gt = b1[c];
#pragma unroll
    for (int q = 0; q < 16; q++) gt += g_gtp[q * 256 + c];
#pragma unroll
    for (int r = 0; r < 4; r++) {
        float pre = (acc[r] + gt) * RSQRT2;
        out_one[(r0 + r) * 256 + c] = (s_in[c * 4 + r] + GAIN * tanh_fast(pre)) * RSQRT2;
    }
}

// ---------------------------------------------------------------------------
// k_two helpers (64-row tile, 128 threads, 4 warps)
// ---------------------------------------------------------------------------
__device__ __forceinline__ void mma_tile(u32 Ah, u32 Bb, float (&acc)[2][8][4]) {
#pragma unroll
    for (int mi = 0; mi < 2; mi++)
#pragma unroll
        for (int nt = 0; nt < 8; nt++)
#pragma unroll
            for (int c = 0; c < 4; c++) acc[mi][nt][c] = 0.f;
#pragma unroll
    for (int ks = 0; ks < 8; ks++) {
        u32 b[4][4], a0[4], a1[4];
#pragma unroll
        for (int nb = 0; nb < 4; nb++) ldsm4(b[nb], Bb + nb * 16 * BSTRIDE + ks * 32);
        ldsm4(a0, Ah + ks * 32);
        ldsm4(a1, Ah + 16 * BSTRIDE + ks * 32);
#pragma unroll
        for (int nb = 0; nb < 4; nb++) {
            mma16816(acc[0][nb * 2 + 0], a0, b[nb]);
            mma16816(acc[0][nb * 2 + 1], a0, b[nb] + 2);
            mma16816(acc[1][nb * 2 + 0], a1, b[nb]);
            mma16816(acc[1][nb * 2 + 1], a1, b[nb] + 2);
        }
    }
}

// stage one 64x128 tile: fp32 -> fp16 into S_AH, column sums into S_RED
__device__ __forceinline__ void stage_tile(char* smem, const float* __restrict__ src,
                                           int rr, int kc) {
    float4 csum = make_float4(0.f, 0.f, 0.f, 0.f);
#pragma unroll
    for (int it = 0; it < 16; it++) {
        int row = rr + it * 4;
        float4 v = *(const float4*)(src + (size_t)it * 4 * 65536);
        csum.x += v.x; csum.y += v.y; csum.z += v.z; csum.w += v.w;
        __half2 h0 = __float22half2_rn(make_float2(v.x, v.y));
        __half2 h1 = __float22half2_rn(make_float2(v.z, v.w));
        u64 hp = (u64)(*(u32*)&h0) | ((u64)(*(u32*)&h1) << 32);
        *(u64*)(smem + S_AH + row * BSTRIDE + kc * 8) = hp;
    }
    *(float4*)(smem + S_RED + (rr * 32 + kc) * 16) = csum;
}

__device__ __forceinline__ void epi_tile(const char* smem, float (&acc)[2][8][4],
                                         const float2* bz, size_t ibase, int j,
                                         int lane, int mw, int nw,
                                         float* __restrict__ out_two) {
    int col0 = nw * 64 + (lane & 3) * 2;
#pragma unroll
    for (int mi = 0; mi < 2; mi++) {
#pragma unroll
        for (int half = 0; half < 2; half++) {
            int rt = mw * 32 + mi * 16 + half * 8 + (lane >> 2);
            float* orow = out_two + ((ibase + rt) * 512 + j) * 128;
#pragma unroll
            for (int nt = 0; nt < 8; nt++) {
                int c = col0 + nt * 8;
                __half2 hh = *(const __half2*)(smem + S_AH + rt * BSTRIDE + c * 2);
                float2 hf = __half22float2(hh);
                float d0 = acc[mi][nt][half * 2 + 0] + bz[nt].x;
                float d1 = acc[mi][nt][half * 2 + 1] + bz[nt].y;
                float2 o;
                o.x = (hf.x + GAIN * tanh_fast(d0)) * RSQRT2;
                o.y = (hf.y + GAIN * tanh_fast(d1)) * RSQRT2;
                *(float2*)(orow + c) = o;
            }
        }
    }
}

// ---------------------------------------------------------------------------
// K3: fp16 mma.sync, 64x128 tiles, j-PAIR per block. grid 2064 x 128 thr.
// blocks < 2048: GEMM; blocks 2048..2063: gt partials.
// bid -> jp = bid&255 (j0=2*jp, j1=j0+1), ch = bid>>8 (0..7), ibase = ch*64.
// ---------------------------------------------------------------------------
__global__ void __launch_bounds__(128, 4)
k_two(const float* __restrict__ h_two,
      const float* __restrict__ b2,
      const float* __restrict__ Wg,
      float* __restrict__ out_two) {
    extern __shared__ char smem[];
    int tid = threadIdx.x;

    if (blockIdx.x >= 2048) {
        // ---- gt partials: block q covers k in [q*32, q*32+32), 2 cols/thread
        __shared__ float s_g1[32];
        int q = blockIdx.x - 2048;
        if (tid < 32) {
            int kk = q * 32 + tid;
            int s = kk >> 8;
            int col = kk & 255;
            float sum = 0.f;
#pragma unroll
            for (int ck = 0; ck < 8; ck++) sum += g_g1p[(s * 8 + ck) * 256 + col];
            s_g1[tid] = sum * INV256;
        }
        __syncthreads();
#pragma unroll
        for (int cc = 0; cc < 2; cc++) {
            int c = tid + cc * 128;
            float acc = 0.f;
#pragma unroll
            for (int kb = 0; kb < 4; kb++) {
                float w[8];
#pragma unroll
                for (int i = 0; i < 8; i++) w[i] = Wg[(q * 32 + kb * 8 + i) * 256 + c];
#pragma unroll
                for (int i = 0; i < 8; i++) acc += s_g1[kb * 8 + i] * w[i];
            }
            g_gtp[q * 256 + c] = acc;
        }
        return;
    }

    u32 sb = smem_u32(smem);
    int lane = tid & 31;
    int w = tid >> 5;              // 0..3

    int jp = blockIdx.x & 255;
    int ch = blockIdx.x >> 8;      // 0..7
    size_t ibase = (size_t)ch * 64;
    int j0 = jp * 2;
    int j1 = j0 + 1;

    int rr = tid >> 5;             // 0..3
    int kc = tid & 31;             // k-quad
    const float* src0 = h_two + (ibase + rr) * 65536 + (size_t)j0 * 128 + kc * 4;
    const float* src1 = src0 + 128;

    // stage W2T fp16 image once per pair: 2176 uint4 / 128 thr = 17 iters
    {
        const uint4* wh = (const uint4*)g_w2h;
        uint4* dh = (uint4*)(smem + S_WH);
        for (int idx = tid; idx < 2176; idx += 128) dh[idx] = wh[idx];
    }

    // stage tile 0, prefetch tile 1 into L2 (register-free)
    stage_tile(smem, src0, rr, kc);
#pragma unroll
    for (int it = 0; it < 16; it++) prefetch_l2(src1 + (size_t)it * 4 * 65536);
    __syncthreads();

    // g2 partial for tile 0 (128 threads, 4 rr-partials each)
    {
        int p = tid;
        float sum = 0.f;
#pragma unroll
        for (int r4 = 0; r4 < 4; r4++)
            sum += *(const float*)(smem + S_RED + (r4 * 32 + (p >> 2)) * 16 + (p & 3) * 4);
        g_g2p[(size_t)ch * 65536 + (size_t)j0 * 128 + p] = sum;
    }

    int mw = w & 1;       // m-block: rows mw*32
    int nw = w >> 1;      // n-block: cols nw*64

    u32 a_off = (u32)((mw * 32 + (lane & 15)) * BSTRIDE + ((lane >> 4) << 4));
    u32 b_off = (u32)((((lane & 7) + ((lane >> 4) << 3)) * BSTRIDE) + (((lane >> 3) & 1) << 4));
    u32 Ah = sb + S_AH + a_off;
    u32 Bb = sb + S_WH + (u32)(nw * 64 * BSTRIDE) + b_off;

    int col0 = nw * 64 + (lane & 3) * 2;
    float2 bz[8];
#pragma unroll
    for (int nt = 0; nt < 8; nt++) bz[nt] = *(const float2*)(b2 + col0 + nt * 8);

    float acc[2][8][4];

    // ---- tile 0 ----
    mma_tile(Ah, Bb, acc);
    epi_tile(smem, acc, bz, ibase, j0, lane, mw, nw, out_two);

    // ---- tile 1 (A loads hit L2) ----
    __syncthreads();
    stage_tile(smem, src1, rr, kc);
    __syncthreads();

    {
        int p = tid;
        float sum = 0.f;
#pragma unroll
        for (int r4 = 0; r4 < 4; r4++)
            sum += *(const float*)(smem + S_RED + (r4 * 32 + (p >> 2)) * 16 + (p & 3) * 4);
        g_g2p[(size_t)ch * 65536 + (size_t)j1 * 128 + p] = sum;
    }

    mma_tile(Ah, Bb, acc);
    epi_tile(smem, acc, bz, ibase, j1, lane, mw, nw, out_two);
}

// ---------------------------------------------------------------------------
extern "C" void kernel_launch(void* const* d_in, const int* in_sizes, int n_in,
                              void* d_out, int out_size) {
    const float* h_one = (const float*)d_in[0];
    const float* h_two = (const float*)d_in[1];
    const float* W1    = (const float*)d_in[2];
    const float* b1    = (const float*)d_in[3];
    const float* Wg    = (const float*)d_in[4];
    const float* W2    = (const float*)d_in[5];
    const float* b2    = (const float*)d_in[6];

    float* out_one = (float*)d_out;
    float* out_two = (float*)d_out + 512 * 256;

    cudaFuncSetAttribute(k_two, cudaFuncAttributeMaxDynamicSharedMemorySize, SMEM_TWO);

    k_prep<<<32, 256>>>(W2, h_one);
    k_two<<<2064, 128, SMEM_TWO>>>(h_two, b2, Wg, out_two);
    k_one<<<128, 256>>>(h_one, W1, b1, out_one);
}

// round 14
// speedup vs baseline: 1.2324x; 1.2324x over previous
#include <cuda_runtime.h>
#include <cuda_fp16.h>
#include <cstdint>

// ---------------------------------------------------------------------------
// FermiLayer: N=512 (256 up / 256 dn), SINGLE=256, PAIR=128
// inputs: [0] h_one (512,256) [1] h_two (512,512,128) [2] W1 (512,256)
//         [3] b1 (256) [4] Wg (512,256) [5] W2 (128,128) [6] b2 (128)
// output: [h_one_out | h_two_out] fp32
// k_two: PERSISTENT fp16 mma.sync. 296 blocks x 256 thr (2 CTA/SM), each
// loops over ~7 128x128 tiles (t += 296). W2 staged ONCE per block; next
// tile's A prefetched to L2 during current tile. g2 partials + gtp fused.
// ---------------------------------------------------------------------------

#define GAIN    1.5927812698663017f
#define RSQRT2  0.7071067811865475f
#define INV256  0.00390625f

#define NBLK 296      // persistent GEMM blocks (148 SMs x 2)
#define NTILE 2048    // total 128x128 tiles

typedef unsigned long long u64;
typedef unsigned int u32;

// scratch (__device__ globals: allocation-free rule)
__device__ float g_g2p[4 * 512 * 128];   // [(s*2+h)][j][p] partials (128 i each)
__device__ float g_g1p[16 * 256];        // g1 partials
__device__ float g_gtp[16 * 256];        // gt partials (16 k-chunks)
__device__ __align__(16) unsigned char g_w2h[35840];  // W2^T fp16, stride 272B

__device__ __forceinline__ float tanh_fast(float x) {
    float y;
    asm("tanh.approx.f32 %0, %1;" : "=f"(y) : "f"(x));
    return y;
}
__device__ __forceinline__ u32 smem_u32(const void* p) {
    u32 a;
    asm("{ .reg .u64 t; cvta.to.shared.u64 t, %1; cvt.u32.u64 %0, t; }" : "=r"(a) : "l"(p));
    return a;
}
__device__ __forceinline__ void ldsm4(u32* r, u32 addr) {
    asm volatile("ldmatrix.sync.aligned.m8n8.x4.shared.b16 {%0,%1,%2,%3}, [%4];"
                 : "=r"(r[0]), "=r"(r[1]), "=r"(r[2]), "=r"(r[3]) : "r"(addr));
}
__device__ __forceinline__ void mma16816(float* c, const u32* a, const u32* b) {
    asm volatile(
        "mma.sync.aligned.m16n8k16.row.col.f32.f16.f16.f32 "
        "{%0,%1,%2,%3}, {%4,%5,%6,%7}, {%8,%9}, {%0,%1,%2,%3};"
        : "+f"(c[0]), "+f"(c[1]), "+f"(c[2]), "+f"(c[3])
        : "r"(a[0]), "r"(a[1]), "r"(a[2]), "r"(a[3]), "r"(b[0]), "r"(b[1]));
}
__device__ __forceinline__ void prefetch_l2(const void* p) {
    asm volatile("prefetch.global.L2 [%0];" :: "l"(p));
}

#define BSTRIDE 272
#define S_AH  0
#define S_WH  34816
#define S_RED 69632
#define SMEM_TWO 73728

// ---------------------------------------------------------------------------
// K0: merged prep. blocks 0..15: W2T fp16 image. blocks 16..31: g1 partials.
// ---------------------------------------------------------------------------
__global__ void k_prep(const float* __restrict__ W2,
                       const float* __restrict__ h_one) {
    int b = blockIdx.x;
    if (b < 16) {
        int t = b * 256 + threadIdx.x;
        int n = t >> 5;
        int k = (t & 31) * 4;
        __half2 h0 = __float22half2_rn(make_float2(W2[(k + 0) * 128 + n], W2[(k + 1) * 128 + n]));
        __half2 h1 = __float22half2_rn(make_float2(W2[(k + 2) * 128 + n], W2[(k + 3) * 128 + n]));
        u64 hp = (u64)(*(u32*)&h0) | ((u64)(*(u32*)&h1) << 32);
        *(u64*)(g_w2h + n * BSTRIDE + k * 2) = hp;
    } else {
        int bb = b - 16;
        int s = bb >> 3, ck = bb & 7;
        int c = threadIdx.x;
        const float* p = h_one + (size_t)(s * 256 + ck * 32) * 256 + c;
        float sum = 0.f;
#pragma unroll 8
        for (int r = 0; r < 32; r++) sum += p[r * 256];
        g_g1p[bb * 256 + c] = sum;
    }
}

// ---------------------------------------------------------------------------
// K2: h_one path. 128 blocks x 256 threads, 4 rows/block.
// ---------------------------------------------------------------------------
__global__ void __launch_bounds__(256)
k_one(const float* __restrict__ h_one,
      const float* __restrict__ W1,
      const float* __restrict__ b1,
      float* __restrict__ out_one) {
    __shared__ float s_in[2048];
    int tid = threadIdx.x;
    int r0 = blockIdx.x * 4;
#pragma unroll
    for (int i = 0; i < 8; i++) {
        int e = tid + i * 256;
        int k = e >> 2;
        int r = e & 3;
        int n = r0 + r;
        float v;
        if (k < 256) {
            v = h_one[n * 256 + k];
        } else {
            int sp = (k < 384) ? 0 : 1;
            int p = k - 256 - sp * 128;
            size_t base = (size_t)(sp * 2) * 65536 + (size_t)n * 128 + p;
            v = (g_g2p[base] + g_g2p[base + 65536]) * INV256;
        }
        s_in[k * 4 + r] = v;
    }
    __syncthreads();

    int c = tid;
    float acc[4] = {0.f, 0.f, 0.f, 0.f};
#pragma unroll 4
    for (int kb = 0; kb < 64; kb++) {
        float w[8];
#pragma unroll
        for (int i = 0; i < 8; i++) w[i] = W1[(kb * 8 + i) * 256 + c];
#pragma unroll
        for (int i = 0; i < 8; i++) {
            float4 a = *(const float4*)(s_in + (kb * 8 + i) * 4);
            acc[0] += a.x * w[i];
            acc[1] += a.y * w[i];
            acc[2] += a.z * w[i];
            acc[3] += a.w * w[i];
        }
    }
    float gt = b1[c];
#pragma unroll
    for (int q = 0; q < 16; q++) gt += g_gtp[q * 256 + c];
#pragma unroll
    for (int r = 0; r < 4; r++) {
        float pre = (acc[r] + gt) * RSQRT2;
        out_one[(r0 + r) * 256 + c] = (s_in[c * 4 + r] + GAIN * tanh_fast(pre)) * RSQRT2;
    }
}

// ---------------------------------------------------------------------------
// k_two helpers (128x128 tile, 256 threads, 8 warps)
// ---------------------------------------------------------------------------
__device__ __forceinline__ void mma_tile(u32 Ah, u32 Bb, float (&acc)[2][8][4]) {
#pragma unroll
    for (int mi = 0; mi < 2; mi++)
#pragma unroll
        for (int nt = 0; nt < 8; nt++)
#pragma unroll
            for (int c = 0; c < 4; c++) acc[mi][nt][c] = 0.f;
#pragma unroll
    for (int ks = 0; ks < 8; ks++) {
        u32 b[4][4], a0[4], a1[4];
#pragma unroll
        for (int nb = 0; nb < 4; nb++) ldsm4(b[nb], Bb + nb * 16 * BSTRIDE + ks * 32);
        ldsm4(a0, Ah + ks * 32);
        ldsm4(a1, Ah + 16 * BSTRIDE + ks * 32);
#pragma unroll
        for (int nb = 0; nb < 4; nb++) {
            mma16816(acc[0][nb * 2 + 0], a0, b[nb]);
            mma16816(acc[0][nb * 2 + 1], a0, b[nb] + 2);
            mma16816(acc[1][nb * 2 + 0], a1, b[nb]);
            mma16816(acc[1][nb * 2 + 1], a1, b[nb] + 2);
        }
    }
}

__device__ __forceinline__ void stage_tile(char* smem, const float* __restrict__ src,
                                           int rr, int kc) {
    float4 csum = make_float4(0.f, 0.f, 0.f, 0.f);
#pragma unroll
    for (int it = 0; it < 16; it++) {
        int row = rr + it * 8;
        float4 v = *(const float4*)(src + (size_t)it * 8 * 65536);
        csum.x += v.x; csum.y += v.y; csum.z += v.z; csum.w += v.w;
        __half2 h0 = __float22half2_rn(make_float2(v.x, v.y));
        __half2 h1 = __float22half2_rn(make_float2(v.z, v.w));
        u64 hp = (u64)(*(u32*)&h0) | ((u64)(*(u32*)&h1) << 32);
        *(u64*)(smem + S_AH + row * BSTRIDE + kc * 8) = hp;
    }
    *(float4*)(smem + S_RED + (rr * 32 + kc) * 16) = csum;
}

__device__ __forceinline__ void epi_tile(const char* smem, float (&acc)[2][8][4],
                                         const float2* bz, size_t ibase, int j,
                                         int lane, int mw, int nw,
                                         float* __restrict__ out_two) {
    int col0 = nw * 64 + (lane & 3) * 2;
#pragma unroll
    for (int mi = 0; mi < 2; mi++) {
#pragma unroll
        for (int half = 0; half < 2; half++) {
            int rt = mw * 32 + mi * 16 + half * 8 + (lane >> 2);
            float* orow = out_two + ((ibase + rt) * 512 + j) * 128;
#pragma unroll
            for (int nt = 0; nt < 8; nt++) {
                int c = col0 + nt * 8;
                __half2 hh = *(const __half2*)(smem + S_AH + rt * BSTRIDE + c * 2);
                float2 hf = __half22float2(hh);
                float d0 = acc[mi][nt][half * 2 + 0] + bz[nt].x;
                float d1 = acc[mi][nt][half * 2 + 1] + bz[nt].y;
                float2 o;
                o.x = (hf.x + GAIN * tanh_fast(d0)) * RSQRT2;
                o.y = (hf.y + GAIN * tanh_fast(d1)) * RSQRT2;
                *(float2*)(orow + c) = o;
            }
        }
    }
}

// ---------------------------------------------------------------------------
// K3: persistent fp16 mma.sync. grid NBLK+16 x 256 threads.
// blocks < NBLK: loop tiles t = bid, bid+NBLK, ... < NTILE.
// tile t: j = t&511, ch = t>>9 (0..3): s=ch>>1, h=ch&1, ibase=s*256+h*128.
// blocks >= NBLK: gt partials.
// ---------------------------------------------------------------------------
__global__ void __launch_bounds__(256, 2)
k_two(const float* __restrict__ h_two,
      const float* __restrict__ b2,
      const float* __restrict__ Wg,
      float* __restrict__ out_two) {
    extern __shared__ char smem[];
    int tid = threadIdx.x;

    if (blockIdx.x >= NBLK) {
        // ---- gt partials: block q covers k in [q*32, q*32+32) ----
        __shared__ float s_g1[32];
        int q = blockIdx.x - NBLK;
        int c = tid;
        if (c < 32) {
            int kk = q * 32 + c;
            int s = kk >> 8;
            int col = kk & 255;
            float sum = 0.f;
#pragma unroll
            for (int ck = 0; ck < 8; ck++) sum += g_g1p[(s * 8 + ck) * 256 + col];
            s_g1[c] = sum * INV256;
        }
        __syncthreads();
        float acc = 0.f;
#pragma unroll
        for (int kb = 0; kb < 4; kb++) {
            float w[8];
#pragma unroll
            for (int i = 0; i < 8; i++) w[i] = Wg[(q * 32 + kb * 8 + i) * 256 + c];
#pragma unroll
            for (int i = 0; i < 8; i++) acc += s_g1[kb * 8 + i] * w[i];
        }
        g_gtp[q * 256 + c] = acc;
        return;
    }

    u32 sb = smem_u32(smem);
    int lane = tid & 31;
    int w = tid >> 5;
    int rr = tid >> 5;             // 0..7 (row group for staging)
    int kc = tid & 31;             // k-quad

    // stage W2T fp16 image ONCE per persistent block
    {
        const uint4* wh = (const uint4*)g_w2h;
        uint4* dh = (uint4*)(smem + S_WH);
        for (int idx = tid; idx < 2176; idx += 256) dh[idx] = wh[idx];
    }

    int mw = w & 3;       // m-block: rows mw*32
    int nw = w >> 2;      // n-block: cols nw*64
    u32 a_off = (u32)((mw * 32 + (lane & 15)) * BSTRIDE + ((lane >> 4) << 4));
    u32 b_off = (u32)((((lane & 7) + ((lane >> 4) << 3)) * BSTRIDE) + (((lane >> 3) & 1) << 4));
    u32 Ah = sb + S_AH + a_off;
    u32 Bb = sb + S_WH + (u32)(nw * 64 * BSTRIDE) + b_off;

    int col0 = nw * 64 + (lane & 3) * 2;
    float2 bz[8];
#pragma unroll
    for (int nt = 0; nt < 8; nt++) bz[nt] = *(const float2*)(b2 + col0 + nt * 8);

    float acc[2][8][4];

    for (int t = blockIdx.x; t < NTILE; t += NBLK) {
        int j = t & 511;
        int ch = t >> 9;
        int s = ch >> 1;
        int h = ch & 1;
        size_t ibase = (size_t)(s * 256 + h * 128);
        const float* src = h_two + (ibase + rr) * 65536 + (size_t)j * 128 + kc * 4;

        stage_tile(smem, src, rr, kc);

        // prefetch next tile's A slice into L2 (register-free)
        int tn = t + NBLK;
        if (tn < NTILE) {
            int jn = tn & 511;
            int chn = tn >> 9;
            size_t ibn = (size_t)((chn >> 1) * 256 + (chn & 1) * 128);
            const float* srcn = h_two + (ibn + rr) * 65536 + (size_t)jn * 128 + kc * 4;
#pragma unroll
            for (int it = 0; it < 16; it++) prefetch_l2(srcn + (size_t)it * 8 * 65536);
        }
        __syncthreads();

        // g2 partial for this tile
        if (tid < 128) {
            int p = tid;
            float sum = 0.f;
#pragma unroll
            for (int r8 = 0; r8 < 8; r8++)
                sum += *(const float*)(smem + S_RED + (r8 * 32 + (p >> 2)) * 16 + (p & 3) * 4);
            g_g2p[(size_t)(s * 2 + h) * 65536 + (size_t)j * 128 + p] = sum;
        }

        mma_tile(Ah, Bb, acc);
        epi_tile(smem, acc, bz, ibase, j, lane, mw, nw, out_two);
        __syncthreads();   // A buffer reused next iteration
    }
}

// ---------------------------------------------------------------------------
extern "C" void kernel_launch(void* const* d_in, const int* in_sizes, int n_in,
                              void* d_out, int out_size) {
    const float* h_one = (const float*)d_in[0];
    const float* h_two = (const float*)d_in[1];
    const float* W1    = (const float*)d_in[2];
    const float* b1    = (const float*)d_in[3];
    const float* Wg    = (const float*)d_in[4];
    const float* W2    = (const float*)d_in[5];
    const float* b2    = (const float*)d_in[6];

    float* out_one = (float*)d_out;
    float* out_two = (float*)d_out + 512 * 256;

    cudaFuncSetAttribute(k_two, cudaFuncAttributeMaxDynamicSharedMemorySize, SMEM_TWO);

    k_prep<<<32, 256>>>(W2, h_one);
    k_two<<<NBLK + 16, 256, SMEM_TWO>>>(h_two, b2, Wg, out_two);
    k_one<<<128, 256>>>(h_one, W1, b1, out_one);
}

// round 15
// speedup vs baseline: 1.2922x; 1.0485x over previous
#include <cuda_runtime.h>
#include <cuda_fp16.h>
#include <cstdint>

// ---------------------------------------------------------------------------
// FermiLayer: N=512 (256 up / 256 dn), SINGLE=256, PAIR=128
// inputs: [0] h_one (512,256) [1] h_two (512,512,128) [2] W1 (512,256)
//         [3] b1 (256) [4] Wg (512,256) [5] W2 (128,128) [6] b2 (128)
// output: [h_one_out | h_two_out] fp32
// TWO launches total:
//  k_two (persistent): GEMM blocks stage W2 directly (transpose+fp16);
//    riding blocks compute gt (incl. g1) and convert W1 -> packed fp16.
//  k_one: h_one path using fp16 W1 (halved traffic).
// ---------------------------------------------------------------------------

#define GAIN    1.5927812698663017f
#define RSQRT2  0.7071067811865475f
#define INV256  0.00390625f

#define NBLK 296      // persistent GEMM blocks (148 SMs x 2)
#define NTILE 2048    // total 128x128 tiles

typedef unsigned long long u64;
typedef unsigned int u32;

// scratch (__device__ globals: allocation-free rule)
__device__ float g_g2p[4 * 512 * 128];   // [(s*2+h)][j][p] partials (128 i each)
__device__ float g_gtp[16 * 256];        // gt partials (16 k-chunks)
__device__ u32 g_w1h[512 * 128];         // W1 fp16 packed: [k][cpair] = (c, c+128)

__device__ __forceinline__ float tanh_fast(float x) {
    float y;
    asm("tanh.approx.f32 %0, %1;" : "=f"(y) : "f"(x));
    return y;
}
__device__ __forceinline__ u32 smem_u32(const void* p) {
    u32 a;
    asm("{ .reg .u64 t; cvta.to.shared.u64 t, %1; cvt.u32.u64 %0, t; }" : "=r"(a) : "l"(p));
    return a;
}
__device__ __forceinline__ void ldsm4(u32* r, u32 addr) {
    asm volatile("ldmatrix.sync.aligned.m8n8.x4.shared.b16 {%0,%1,%2,%3}, [%4];"
                 : "=r"(r[0]), "=r"(r[1]), "=r"(r[2]), "=r"(r[3]) : "r"(addr));
}
__device__ __forceinline__ void mma16816(float* c, const u32* a, const u32* b) {
    asm volatile(
        "mma.sync.aligned.m16n8k16.row.col.f32.f16.f16.f32 "
        "{%0,%1,%2,%3}, {%4,%5,%6,%7}, {%8,%9}, {%0,%1,%2,%3};"
        : "+f"(c[0]), "+f"(c[1]), "+f"(c[2]), "+f"(c[3])
        : "r"(a[0]), "r"(a[1]), "r"(a[2]), "r"(a[3]), "r"(b[0]), "r"(b[1]));
}
__device__ __forceinline__ void prefetch_l2(const void* p) {
    asm volatile("prefetch.global.L2 [%0];" :: "l"(p));
}

#define BSTRIDE 272
#define S_AH  0
#define S_WH  34816
#define S_RED 69632
#define SMEM_TWO 73728

// ---------------------------------------------------------------------------
// K2: h_one path. 128 blocks x 256 threads, 4 rows/block, fp16 W1 packed.
// thread: cpair = tid&127 (cols cpair, cpair+128), rhalf = tid>>7 (2 rows).
// ---------------------------------------------------------------------------
__global__ void __launch_bounds__(256)
k_one(const float* __restrict__ h_one,
      const float* __restrict__ b1,
      float* __restrict__ out_one) {
    __shared__ float s_in[2048];   // [k][r], k=0..511, r=0..3
    int tid = threadIdx.x;
    int r0 = blockIdx.x * 4;
#pragma unroll
    for (int i = 0; i < 8; i++) {
        int e = tid + i * 256;
        int k = e >> 2;
        int r = e & 3;
        int n = r0 + r;
        float v;
        if (k < 256) {
            v = h_one[n * 256 + k];
        } else {
            int sp = (k < 384) ? 0 : 1;
            int p = k - 256 - sp * 128;
            size_t base = (size_t)(sp * 2) * 65536 + (size_t)n * 128 + p;
            v = (g_g2p[base] + g_g2p[base + 65536]) * INV256;
        }
        s_in[k * 4 + r] = v;
    }
    __syncthreads();

    int cpair = tid & 127;
    int rhalf = tid >> 7;          // rows r0+rhalf*2, +1
    float acc00 = 0.f, acc01 = 0.f, acc10 = 0.f, acc11 = 0.f;
#pragma unroll 4
    for (int kb = 0; kb < 64; kb++) {
        u32 wp[8];
#pragma unroll
        for (int i = 0; i < 8; i++) wp[i] = g_w1h[(kb * 8 + i) * 128 + cpair];
#pragma unroll
        for (int i = 0; i < 8; i++) {
            float2 w = __half22float2(*(__half2*)&wp[i]);
            float2 a = *(const float2*)(s_in + (kb * 8 + i) * 4 + rhalf * 2);
            acc00 += a.x * w.x;   // row0, col cpair
            acc01 += a.x * w.y;   // row0, col cpair+128
            acc10 += a.y * w.x;
            acc11 += a.y * w.y;
        }
    }
    float gt0 = b1[cpair], gt1 = b1[cpair + 128];
#pragma unroll
    for (int q = 0; q < 16; q++) {
        gt0 += g_gtp[q * 256 + cpair];
        gt1 += g_gtp[q * 256 + cpair + 128];
    }
    int rA = r0 + rhalf * 2, rB = rA + 1;
    out_one[rA * 256 + cpair]       = (s_in[cpair * 4 + rhalf * 2]           + GAIN * tanh_fast((acc00 + gt0) * RSQRT2)) * RSQRT2;
    out_one[rB * 256 + cpair]       = (s_in[cpair * 4 + rhalf * 2 + 1]       + GAIN * tanh_fast((acc10 + gt0) * RSQRT2)) * RSQRT2;
    out_one[rA * 256 + cpair + 128] = (s_in[(cpair + 128) * 4 + rhalf * 2]     + GAIN * tanh_fast((acc01 + gt1) * RSQRT2)) * RSQRT2;
    out_one[rB * 256 + cpair + 128] = (s_in[(cpair + 128) * 4 + rhalf * 2 + 1] + GAIN * tanh_fast((acc11 + gt1) * RSQRT2)) * RSQRT2;
}

// ---------------------------------------------------------------------------
// k_two helpers (128x128 tile, 256 threads, 8 warps)
// ---------------------------------------------------------------------------
__device__ __forceinline__ void mma_tile(u32 Ah, u32 Bb, float (&acc)[2][8][4]) {
#pragma unroll
    for (int mi = 0; mi < 2; mi++)
#pragma unroll
        for (int nt = 0; nt < 8; nt++)
#pragma unroll
            for (int c = 0; c < 4; c++) acc[mi][nt][c] = 0.f;
#pragma unroll
    for (int ks = 0; ks < 8; ks++) {
        u32 b[4][4], a0[4], a1[4];
#pragma unroll
        for (int nb = 0; nb < 4; nb++) ldsm4(b[nb], Bb + nb * 16 * BSTRIDE + ks * 32);
        ldsm4(a0, Ah + ks * 32);
        ldsm4(a1, Ah + 16 * BSTRIDE + ks * 32);
#pragma unroll
        for (int nb = 0; nb < 4; nb++) {
            mma16816(acc[0][nb * 2 + 0], a0, b[nb]);
            mma16816(acc[0][nb * 2 + 1], a0, b[nb] + 2);
            mma16816(acc[1][nb * 2 + 0], a1, b[nb]);
            mma16816(acc[1][nb * 2 + 1], a1, b[nb] + 2);
        }
    }
}

__device__ __forceinline__ void stage_tile(char* smem, const float* __restrict__ src,
                                           int rr, int kc) {
    float4 csum = make_float4(0.f, 0.f, 0.f, 0.f);
#pragma unroll
    for (int it = 0; it < 16; it++) {
        int row = rr + it * 8;
        float4 v = *(const float4*)(src + (size_t)it * 8 * 65536);
        csum.x += v.x; csum.y += v.y; csum.z += v.z; csum.w += v.w;
        __half2 h0 = __float22half2_rn(make_float2(v.x, v.y));
        __half2 h1 = __float22half2_rn(make_float2(v.z, v.w));
        u64 hp = (u64)(*(u32*)&h0) | ((u64)(*(u32*)&h1) << 32);
        *(u64*)(smem + S_AH + row * BSTRIDE + kc * 8) = hp;
    }
    *(float4*)(smem + S_RED + (rr * 32 + kc) * 16) = csum;
}

__device__ __forceinline__ void epi_tile(const char* smem, float (&acc)[2][8][4],
                                         const float2* bz, size_t ibase, int j,
                                         int lane, int mw, int nw,
                                         float* __restrict__ out_two) {
    int col0 = nw * 64 + (lane & 3) * 2;
#pragma unroll
    for (int mi = 0; mi < 2; mi++) {
#pragma unroll
        for (int half = 0; half < 2; half++) {
            int rt = mw * 32 + mi * 16 + half * 8 + (lane >> 2);
            float* orow = out_two + ((ibase + rt) * 512 + j) * 128;
#pragma unroll
            for (int nt = 0; nt < 8; nt++) {
                int c = col0 + nt * 8;
                __half2 hh = *(const __half2*)(smem + S_AH + rt * BSTRIDE + c * 2);
                float2 hf = __half22float2(hh);
                float d0 = acc[mi][nt][half * 2 + 0] + bz[nt].x;
                float d1 = acc[mi][nt][half * 2 + 1] + bz[nt].y;
                float2 o;
                o.x = (hf.x + GAIN * tanh_fast(d0)) * RSQRT2;
                o.y = (hf.y + GAIN * tanh_fast(d1)) * RSQRT2;
                *(float2*)(orow + c) = o;
            }
        }
    }
}

// ---------------------------------------------------------------------------
// K3: persistent fp16 mma.sync. grid NBLK+32 x 256 threads.
// blocks < NBLK: GEMM, loop t = bid; t < NTILE; t += NBLK. W2 staged directly
//   from global (transpose+convert) ONCE per block.
// blocks NBLK..NBLK+15: gt partials (compute own g1 from h_one).
// blocks NBLK+16..NBLK+31: W1 -> packed fp16 conversion.
// ---------------------------------------------------------------------------
__global__ void __launch_bounds__(256, 2)
k_two(const float* __restrict__ h_two,
      const float* __restrict__ b2,
      const float* __restrict__ Wg,
      const float* __restrict__ W2,
      const float* __restrict__ W1,
      const float* __restrict__ h_one,
      float* __restrict__ out_two) {
    extern __shared__ char smem[];
    int tid = threadIdx.x;

    if (blockIdx.x >= NBLK + 16) {
        // ---- W1 conversion: block q covers k in [q*32, q*32+32) ----
        int q = blockIdx.x - NBLK - 16;
        int cpair = tid & 127;
        int kh = tid >> 7;          // 0..1
#pragma unroll
        for (int kk = 0; kk < 16; kk++) {
            int k = q * 32 + kh * 16 + kk;
            float w0 = W1[k * 256 + cpair];
            float w1 = W1[k * 256 + cpair + 128];
            __half2 h = __float22half2_rn(make_float2(w0, w1));
            g_w1h[k * 128 + cpair] = *(u32*)&h;
        }
        return;
    }

    if (blockIdx.x >= NBLK) {
        // ---- gt partials: block q covers k in [q*32, q*32+32); own g1 ----
        __shared__ float s_part[8][32];
        __shared__ float s_g1[32];
        int q = blockIdx.x - NBLK;
        {
            int i = tid & 31;       // which kk
            int chk = tid >> 5;     // row chunk 0..7
            int kk = q * 32 + i;
            int sP = kk >> 8;
            int col = kk & 255;
            const float* p = h_one + (size_t)(sP * 256 + chk * 32) * 256 + col;
            float sum = 0.f;
#pragma unroll 8
            for (int r = 0; r < 32; r++) sum += p[r * 256];
            s_part[chk][i] = sum;
        }
        __syncthreads();
        if (tid < 32) {
            float t = 0.f;
#pragma unroll
            for (int c8 = 0; c8 < 8; c8++) t += s_part[c8][tid];
            s_g1[tid] = t * INV256;
        }
        __syncthreads();
        int c = tid;
        float acc = 0.f;
#pragma unroll
        for (int kb = 0; kb < 4; kb++) {
            float w[8];
#pragma unroll
            for (int i = 0; i < 8; i++) w[i] = Wg[(q * 32 + kb * 8 + i) * 256 + c];
#pragma unroll
            for (int i = 0; i < 8; i++) acc += s_g1[kb * 8 + i] * w[i];
        }
        g_gtp[q * 256 + c] = acc;
        return;
    }

    u32 sb = smem_u32(smem);
    int lane = tid & 31;
    int w = tid >> 5;
    int rr = tid >> 5;             // 0..7 (row group for staging)
    int kc = tid & 31;             // k-quad

    // stage W2T fp16 image ONCE per block, directly from W2 (transpose+cvt)
    {
        int n = tid & 127;
        int kh = tid >> 7;          // 0..1 (k halves 0..63 / 64..127)
#pragma unroll
        for (int kk = 0; kk < 32; kk++) {
            int k = kh * 64 + kk * 2;
            float w0 = W2[k * 128 + n];
            float w1 = W2[(k + 1) * 128 + n];
            __half2 h = __float22half2_rn(make_float2(w0, w1));
            *(__half2*)(smem + S_WH + n * BSTRIDE + k * 2) = h;
        }
    }

    int mw = w & 3;       // m-block: rows mw*32
    int nw = w >> 2;      // n-block: cols nw*64
    u32 a_off = (u32)((mw * 32 + (lane & 15)) * BSTRIDE + ((lane >> 4) << 4));
    u32 b_off = (u32)((((lane & 7) + ((lane >> 4) << 3)) * BSTRIDE) + (((lane >> 3) & 1) << 4));
    u32 Ah = sb + S_AH + a_off;
    u32 Bb = sb + S_WH + (u32)(nw * 64 * BSTRIDE) + b_off;

    int col0 = nw * 64 + (lane & 3) * 2;
    float2 bz[8];
#pragma unroll
    for (int nt = 0; nt < 8; nt++) bz[nt] = *(const float2*)(b2 + col0 + nt * 8);

    float acc[2][8][4];

    for (int t = blockIdx.x; t < NTILE; t += NBLK) {
        int j = t & 511;
        int ch = t >> 9;
        int s = ch >> 1;
        int h = ch & 1;
        size_t ibase = (size_t)(s * 256 + h * 128);
        const float* src = h_two + (ibase + rr) * 65536 + (size_t)j * 128 + kc * 4;

        stage_tile(smem, src, rr, kc);

        // prefetch next tile's A slice into L2 (register-free)
        int tn = t + NBLK;
        if (tn < NTILE) {
            int jn = tn & 511;
            int chn = tn >> 9;
            size_t ibn = (size_t)((chn >> 1) * 256 + (chn & 1) * 128);
            const float* srcn = h_two + (ibn + rr) * 65536 + (size_t)jn * 128 + kc * 4;
#pragma unroll
            for (int it = 0; it < 16; it++) prefetch_l2(srcn + (size_t)it * 8 * 65536);
        }
        __syncthreads();

        // g2 partial for this tile
        if (tid < 128) {
            int p = tid;
            float sum = 0.f;
#pragma unroll
            for (int r8 = 0; r8 < 8; r8++)
                sum += *(const float*)(smem + S_RED + (r8 * 32 + (p >> 2)) * 16 + (p & 3) * 4);
            g_g2p[(size_t)(s * 2 + h) * 65536 + (size_t)j * 128 + p] = sum;
        }

        mma_tile(Ah, Bb, acc);
        epi_tile(smem, acc, bz, ibase, j, lane, mw, nw, out_two);
        __syncthreads();   // A buffer reused next iteration
    }
}

// ---------------------------------------------------------------------------
extern "C" void kernel_launch(void* const* d_in, const int* in_sizes, int n_in,
                              void* d_out, int out_size) {
    const float* h_one = (const float*)d_in[0];
    const float* h_two = (const float*)d_in[1];
    const float* W1    = (const float*)d_in[2];
    const float* b1    = (const float*)d_in[3];
    const float* Wg    = (const float*)d_in[4];
    const float* W2    = (const float*)d_in[5];
    const float* b2    = (const float*)d_in[6];

    float* out_one = (float*)d_out;
    float* out_two = (float*)d_out + 512 * 256;

    cudaFuncSetAttribute(k_two, cudaFuncAttributeMaxDynamicSharedMemorySize, SMEM_TWO);

    k_two<<<NBLK + 32, 256, SMEM_TWO>>>(h_two, b2, Wg, W2, W1, h_one, out_two);
    k_one<<<128, 256>>>(h_one, b1, out_one);
}

// round 16
// speedup vs baseline: 1.3095x; 1.0134x over previous
#include <cuda_runtime.h>
#include <cuda_fp16.h>
#include <cstdint>

// ---------------------------------------------------------------------------
// FermiLayer: N=512 (256 up / 256 dn), SINGLE=256, PAIR=128
// inputs: [0] h_one (512,256) [1] h_two (512,512,128) [2] W1 (512,256)
//         [3] b1 (256) [4] Wg (512,256) [5] W2 (128,128) [6] b2 (128)
// output: [h_one_out | h_two_out] fp32
// k_two (persistent): riding blocks FIRST (bid 0..31: gtp + W1->fp16), GEMM
// blocks bid 32.. (so riding work overlaps GEMM instead of trailing it).
// k_one: 256 blocks x 2 rows, software-prefetched fp16 W1.
// ---------------------------------------------------------------------------

#define GAIN    1.5927812698663017f
#define RSQRT2  0.7071067811865475f
#define INV256  0.00390625f

#define NBLK 296      // persistent GEMM blocks (148 SMs x 2)
#define NTILE 2048    // total 128x128 tiles

typedef unsigned long long u64;
typedef unsigned int u32;

// scratch (__device__ globals: allocation-free rule)
__device__ float g_g2p[4 * 512 * 128];   // [(s*2+h)][j][p] partials (128 i each)
__device__ float g_gtp[16 * 256];        // gt partials (16 k-chunks)
__device__ u32 g_w1h[512 * 128];         // W1 fp16 packed: [k][cpair] = (c, c+128)

__device__ __forceinline__ float tanh_fast(float x) {
    float y;
    asm("tanh.approx.f32 %0, %1;" : "=f"(y) : "f"(x));
    return y;
}
__device__ __forceinline__ u32 smem_u32(const void* p) {
    u32 a;
    asm("{ .reg .u64 t; cvta.to.shared.u64 t, %1; cvt.u32.u64 %0, t; }" : "=r"(a) : "l"(p));
    return a;
}
__device__ __forceinline__ void ldsm4(u32* r, u32 addr) {
    asm volatile("ldmatrix.sync.aligned.m8n8.x4.shared.b16 {%0,%1,%2,%3}, [%4];"
                 : "=r"(r[0]), "=r"(r[1]), "=r"(r[2]), "=r"(r[3]) : "r"(addr));
}
__device__ __forceinline__ void mma16816(float* c, const u32* a, const u32* b) {
    asm volatile(
        "mma.sync.aligned.m16n8k16.row.col.f32.f16.f16.f32 "
        "{%0,%1,%2,%3}, {%4,%5,%6,%7}, {%8,%9}, {%0,%1,%2,%3};"
        : "+f"(c[0]), "+f"(c[1]), "+f"(c[2]), "+f"(c[3])
        : "r"(a[0]), "r"(a[1]), "r"(a[2]), "r"(a[3]), "r"(b[0]), "r"(b[1]));
}
__device__ __forceinline__ void prefetch_l2(const void* p) {
    asm volatile("prefetch.global.L2 [%0];" :: "l"(p));
}

#define BSTRIDE 272
#define S_AH  0
#define S_WH  34816
#define S_RED 69632
#define SMEM_TWO 73728

// ---------------------------------------------------------------------------
// K2: h_one path. 256 blocks x 256 threads, 2 rows/block.
// thread: cpair = tid&127 (cols cpair, cpair+128), rhalf = tid>>7 (1 row).
// W1h loads software-pipelined one kb ahead.
// ---------------------------------------------------------------------------
__global__ void __launch_bounds__(256)
k_one(const float* __restrict__ h_one,
      const float* __restrict__ b1,
      float* __restrict__ out_one) {
    __shared__ float s_in[1024];   // [k][r], k=0..511, r=0..1
    int tid = threadIdx.x;
    int r0 = blockIdx.x * 2;
#pragma unroll
    for (int i = 0; i < 4; i++) {
        int e = tid + i * 256;     // 0..1023
        int k = e >> 1;
        int r = e & 1;
        int n = r0 + r;
        float v;
        if (k < 256) {
            v = h_one[n * 256 + k];
        } else {
            int sp = (k < 384) ? 0 : 1;
            int p = k - 256 - sp * 128;
            size_t base = (size_t)(sp * 2) * 65536 + (size_t)n * 128 + p;
            v = (g_g2p[base] + g_g2p[base + 65536]) * INV256;
        }
        s_in[k * 2 + r] = v;
    }
    __syncthreads();

    int cpair = tid & 127;
    int rhalf = tid >> 7;          // row r0 + rhalf
    float acc0 = 0.f, acc1 = 0.f;

    u32 wp[8], wpn[8];
#pragma unroll
    for (int i = 0; i < 8; i++) wp[i] = g_w1h[i * 128 + cpair];

#pragma unroll 8
    for (int kb = 0; kb < 64; kb++) {
        if (kb < 63) {
#pragma unroll
            for (int i = 0; i < 8; i++) wpn[i] = g_w1h[((kb + 1) * 8 + i) * 128 + cpair];
        }
#pragma unroll
        for (int i = 0; i < 8; i++) {
            float2 w = __half22float2(*(__half2*)&wp[i]);
            float a = s_in[(kb * 8 + i) * 2 + rhalf];
            acc0 += a * w.x;
            acc1 += a * w.y;
        }
#pragma unroll
        for (int i = 0; i < 8; i++) wp[i] = wpn[i];
    }

    float gt0 = b1[cpair], gt1 = b1[cpair + 128];
#pragma unroll
    for (int q = 0; q < 16; q++) {
        gt0 += g_gtp[q * 256 + cpair];
        gt1 += g_gtp[q * 256 + cpair + 128];
    }
    int row = r0 + rhalf;
    out_one[row * 256 + cpair]       = (s_in[cpair * 2 + rhalf]         + GAIN * tanh_fast((acc0 + gt0) * RSQRT2)) * RSQRT2;
    out_one[row * 256 + cpair + 128] = (s_in[(cpair + 128) * 2 + rhalf] + GAIN * tanh_fast((acc1 + gt1) * RSQRT2)) * RSQRT2;
}

// ---------------------------------------------------------------------------
// k_two helpers (128x128 tile, 256 threads, 8 warps)
// ---------------------------------------------------------------------------
__device__ __forceinline__ void mma_tile(u32 Ah, u32 Bb, float (&acc)[2][8][4]) {
#pragma unroll
    for (int mi = 0; mi < 2; mi++)
#pragma unroll
        for (int nt = 0; nt < 8; nt++)
#pragma unroll
            for (int c = 0; c < 4; c++) acc[mi][nt][c] = 0.f;
#pragma unroll
    for (int ks = 0; ks < 8; ks++) {
        u32 b[4][4], a0[4], a1[4];
#pragma unroll
        for (int nb = 0; nb < 4; nb++) ldsm4(b[nb], Bb + nb * 16 * BSTRIDE + ks * 32);
        ldsm4(a0, Ah + ks * 32);
        ldsm4(a1, Ah + 16 * BSTRIDE + ks * 32);
#pragma unroll
        for (int nb = 0; nb < 4; nb++) {
            mma16816(acc[0][nb * 2 + 0], a0, b[nb]);
            mma16816(acc[0][nb * 2 + 1], a0, b[nb] + 2);
            mma16816(acc[1][nb * 2 + 0], a1, b[nb]);
            mma16816(acc[1][nb * 2 + 1], a1, b[nb] + 2);
        }
    }
}

__device__ __forceinline__ void stage_tile(char* smem, const float* __restrict__ src,
                                           int rr, int kc) {
    float4 csum = make_float4(0.f, 0.f, 0.f, 0.f);
#pragma unroll
    for (int it = 0; it < 16; it++) {
        int row = rr + it * 8;
        float4 v = *(const float4*)(src + (size_t)it * 8 * 65536);
        csum.x += v.x; csum.y += v.y; csum.z += v.z; csum.w += v.w;
        __half2 h0 = __float22half2_rn(make_float2(v.x, v.y));
        __half2 h1 = __float22half2_rn(make_float2(v.z, v.w));
        u64 hp = (u64)(*(u32*)&h0) | ((u64)(*(u32*)&h1) << 32);
        *(u64*)(smem + S_AH + row * BSTRIDE + kc * 8) = hp;
    }
    *(float4*)(smem + S_RED + (rr * 32 + kc) * 16) = csum;
}

__device__ __forceinline__ void epi_tile(const char* smem, float (&acc)[2][8][4],
                                         const float2* bz, size_t ibase, int j,
                                         int lane, int mw, int nw,
                                         float* __restrict__ out_two) {
    int col0 = nw * 64 + (lane & 3) * 2;
#pragma unroll
    for (int mi = 0; mi < 2; mi++) {
#pragma unroll
        for (int half = 0; half < 2; half++) {
            int rt = mw * 32 + mi * 16 + half * 8 + (lane >> 2);
            float* orow = out_two + ((ibase + rt) * 512 + j) * 128;
#pragma unroll
            for (int nt = 0; nt < 8; nt++) {
                int c = col0 + nt * 8;
                __half2 hh = *(const __half2*)(smem + S_AH + rt * BSTRIDE + c * 2);
                float2 hf = __half22float2(hh);
                float d0 = acc[mi][nt][half * 2 + 0] + bz[nt].x;
                float d1 = acc[mi][nt][half * 2 + 1] + bz[nt].y;
                float2 o;
                o.x = (hf.x + GAIN * tanh_fast(d0)) * RSQRT2;
                o.y = (hf.y + GAIN * tanh_fast(d1)) * RSQRT2;
                *(float2*)(orow + c) = o;
            }
        }
    }
}

// ---------------------------------------------------------------------------
// K3: persistent fp16 mma.sync. grid NBLK+32 x 256 threads.
// bid 0..15:  gt partials (compute own g1)      — run FIRST, overlap GEMM
// bid 16..31: W1 -> packed fp16 conversion      — run FIRST, overlap GEMM
// bid 32..:   GEMM, loop t = bid-32; t < NTILE; t += NBLK. W2 staged once.
// ---------------------------------------------------------------------------
__global__ void __launch_bounds__(256, 2)
k_two(const float* __restrict__ h_two,
      const float* __restrict__ b2,
      const float* __restrict__ Wg,
      const float* __restrict__ W2,
      const float* __restrict__ W1,
      const float* __restrict__ h_one,
      float* __restrict__ out_two) {
    extern __shared__ char smem[];
    int tid = threadIdx.x;

    if (blockIdx.x < 16) {
        // ---- gt partials: block q covers k in [q*32, q*32+32); own g1 ----
        __shared__ float s_part[8][32];
        __shared__ float s_g1[32];
        int q = blockIdx.x;
        {
            int i = tid & 31;
            int chk = tid >> 5;
            int kk = q * 32 + i;
            int sP = kk >> 8;
            int col = kk & 255;
            const float* p = h_one + (size_t)(sP * 256 + chk * 32) * 256 + col;
            float sum = 0.f;
#pragma unroll 8
            for (int r = 0; r < 32; r++) sum += p[r * 256];
            s_part[chk][i] = sum;
        }
        __syncthreads();
        if (tid < 32) {
            float t = 0.f;
#pragma unroll
            for (int c8 = 0; c8 < 8; c8++) t += s_part[c8][tid];
            s_g1[tid] = t * INV256;
        }
        __syncthreads();
        int c = tid;
        float acc = 0.f;
#pragma unroll
        for (int kb = 0; kb < 4; kb++) {
            float w[8];
#pragma unroll
            for (int i = 0; i < 8; i++) w[i] = Wg[(q * 32 + kb * 8 + i) * 256 + c];
#pragma unroll
            for (int i = 0; i < 8; i++) acc += s_g1[kb * 8 + i] * w[i];
        }
        g_gtp[q * 256 + c] = acc;
        return;
    }

    if (blockIdx.x < 32) {
        // ---- W1 conversion: block q covers k in [q*32, q*32+32) ----
        int q = blockIdx.x - 16;
        int cpair = tid & 127;
        int kh = tid >> 7;
#pragma unroll
        for (int kk = 0; kk < 16; kk++) {
            int k = q * 32 + kh * 16 + kk;
            float w0 = W1[k * 256 + cpair];
            float w1 = W1[k * 256 + cpair + 128];
            __half2 h = __float22half2_rn(make_float2(w0, w1));
            g_w1h[k * 128 + cpair] = *(u32*)&h;
        }
        return;
    }

    u32 sb = smem_u32(smem);
    int lane = tid & 31;
    int w = tid >> 5;
    int rr = tid >> 5;             // 0..7 (row group for staging)
    int kc = tid & 31;             // k-quad

    // stage W2T fp16 image ONCE per block, directly from W2 (transpose+cvt)
    {
        int n = tid & 127;
        int kh = tid >> 7;
#pragma unroll
        for (int kk = 0; kk < 32; kk++) {
            int k = kh * 64 + kk * 2;
            float w0 = W2[k * 128 + n];
            float w1 = W2[(k + 1) * 128 + n];
            __half2 h = __float22half2_rn(make_float2(w0, w1));
            *(__half2*)(smem + S_WH + n * BSTRIDE + k * 2) = h;
        }
    }

    int mw = w & 3;
    int nw = w >> 2;
    u32 a_off = (u32)((mw * 32 + (lane & 15)) * BSTRIDE + ((lane >> 4) << 4));
    u32 b_off = (u32)((((lane & 7) + ((lane >> 4) << 3)) * BSTRIDE) + (((lane >> 3) & 1) << 4));
    u32 Ah = sb + S_AH + a_off;
    u32 Bb = sb + S_WH + (u32)(nw * 64 * BSTRIDE) + b_off;

    int col0 = nw * 64 + (lane & 3) * 2;
    float2 bz[8];
#pragma unroll
    for (int nt = 0; nt < 8; nt++) bz[nt] = *(const float2*)(b2 + col0 + nt * 8);

    float acc[2][8][4];

    for (int t = blockIdx.x - 32; t < NTILE; t += NBLK) {
        int j = t & 511;
        int ch = t >> 9;
        int s = ch >> 1;
        int h = ch & 1;
        size_t ibase = (size_t)(s * 256 + h * 128);
        const float* src = h_two + (ibase + rr) * 65536 + (size_t)j * 128 + kc * 4;

        stage_tile(smem, src, rr, kc);

        // prefetch next tile's A slice into L2 (register-free)
        int tn = t + NBLK;
        if (tn < NTILE) {
            int jn = tn & 511;
            int chn = tn >> 9;
            size_t ibn = (size_t)((chn >> 1) * 256 + (chn & 1) * 128);
            const float* srcn = h_two + (ibn + rr) * 65536 + (size_t)jn * 128 + kc * 4;
#pragma unroll
            for (int it = 0; it < 16; it++) prefetch_l2(srcn + (size_t)it * 8 * 65536);
        }
        __syncthreads();

        // g2 partial for this tile
        if (tid < 128) {
            int p = tid;
            float sum = 0.f;
#pragma unroll
            for (int r8 = 0; r8 < 8; r8++)
                sum += *(const float*)(smem + S_RED + (r8 * 32 + (p >> 2)) * 16 + (p & 3) * 4);
            g_g2p[(size_t)(s * 2 + h) * 65536 + (size_t)j * 128 + p] = sum;
        }

        mma_tile(Ah, Bb, acc);
        epi_tile(smem, acc, bz, ibase, j, lane, mw, nw, out_two);
        __syncthreads();   // A buffer reused next iteration
    }
}

// ---------------------------------------------------------------------------
extern "C" void kernel_launch(void* const* d_in, const int* in_sizes, int n_in,
                              void* d_out, int out_size) {
    const float* h_one = (const float*)d_in[0];
    const float* h_two = (const float*)d_in[1];
    const float* W1    = (const float*)d_in[2];
    const float* b1    = (const float*)d_in[3];
    const float* Wg    = (const float*)d_in[4];
    const float* W2    = (const float*)d_in[5];
    const float* b2    = (const float*)d_in[6];

    float* out_one = (float*)d_out;
    float* out_two = (float*)d_out + 512 * 256;

    cudaFuncSetAttribute(k_two, cudaFuncAttributeMaxDynamicSharedMemorySize, SMEM_TWO);

    k_two<<<NBLK + 32, 256, SMEM_TWO>>>(h_two, b2, Wg, W2, W1, h_one, out_two);
    k_one<<<256, 256>>>(h_one, b1, out_one);
}

// round 17
// speedup vs baseline: 1.5507x; 1.1842x over previous
#include <cuda_runtime.h>
#include <cuda_fp16.h>
#include <cstdint>

// ---------------------------------------------------------------------------
// FermiLayer: N=512 (256 up / 256 dn), SINGLE=256, PAIR=128
// inputs: [0] h_one (512,256) [1] h_two (512,512,128) [2] W1 (512,256)
//         [3] b1 (256) [4] Wg (512,256) [5] W2 (128,128) [6] b2 (128)
// output: [h_one_out | h_two_out] fp32
// k_two (persistent): riding blocks first (gtp + W1->fp16), GEMM blocks after.
// k_one: 256 blocks x 2 rows; 4-deep LDG staging buffers + split FMA chains
// (fixes the regs=32 ILP collapse seen in round 16: issue was 21%).
// ---------------------------------------------------------------------------

#define GAIN    1.5927812698663017f
#define RSQRT2  0.7071067811865475f
#define INV256  0.00390625f

#define NBLK 296      // persistent GEMM blocks (148 SMs x 2)
#define NTILE 2048    // total 128x128 tiles

typedef unsigned long long u64;
typedef unsigned int u32;

// scratch (__device__ globals: allocation-free rule)
__device__ float g_g2p[4 * 512 * 128];   // [(s*2+h)][j][p] partials (128 i each)
__device__ float g_gtp[16 * 256];        // gt partials (16 k-chunks)
__device__ u32 g_w1h[512 * 128];         // W1 fp16 packed: [k][cpair] = (c, c+128)

__device__ __forceinline__ float tanh_fast(float x) {
    float y;
    asm("tanh.approx.f32 %0, %1;" : "=f"(y) : "f"(x));
    return y;
}
__device__ __forceinline__ u32 smem_u32(const void* p) {
    u32 a;
    asm("{ .reg .u64 t; cvta.to.shared.u64 t, %1; cvt.u32.u64 %0, t; }" : "=r"(a) : "l"(p));
    return a;
}
__device__ __forceinline__ void ldsm4(u32* r, u32 addr) {
    asm volatile("ldmatrix.sync.aligned.m8n8.x4.shared.b16 {%0,%1,%2,%3}, [%4];"
                 : "=r"(r[0]), "=r"(r[1]), "=r"(r[2]), "=r"(r[3]) : "r"(addr));
}
__device__ __forceinline__ void mma16816(float* c, const u32* a, const u32* b) {
    asm volatile(
        "mma.sync.aligned.m16n8k16.row.col.f32.f16.f16.f32 "
        "{%0,%1,%2,%3}, {%4,%5,%6,%7}, {%8,%9}, {%0,%1,%2,%3};"
        : "+f"(c[0]), "+f"(c[1]), "+f"(c[2]), "+f"(c[3])
        : "r"(a[0]), "r"(a[1]), "r"(a[2]), "r"(a[3]), "r"(b[0]), "r"(b[1]));
}
__device__ __forceinline__ void prefetch_l2(const void* p) {
    asm volatile("prefetch.global.L2 [%0];" :: "l"(p));
}

#define BSTRIDE 272
#define S_AH  0
#define S_WH  34816
#define S_RED 69632
#define SMEM_TWO 73728

// ---------------------------------------------------------------------------
// K2: h_one path. 256 blocks x 256 threads, 2 rows/block.
// thread: cpair = tid&127 (cols cpair, cpair+128), rhalf = tid>>7 (1 row).
// 4-deep staging buffers (wb[4][8]) + 2 FMA chains per column.
// ---------------------------------------------------------------------------
__global__ void __launch_bounds__(256)
k_one(const float* __restrict__ h_one,
      const float* __restrict__ b1,
      float* __restrict__ out_one) {
    __shared__ float s_in[1024];   // [k][r], k=0..511, r=0..1
    int tid = threadIdx.x;
    int r0 = blockIdx.x * 2;
#pragma unroll
    for (int i = 0; i < 4; i++) {
        int e = tid + i * 256;     // 0..1023
        int k = e >> 1;
        int r = e & 1;
        int n = r0 + r;
        float v;
        if (k < 256) {
            v = h_one[n * 256 + k];
        } else {
            int sp = (k < 384) ? 0 : 1;
            int p = k - 256 - sp * 128;
            size_t base = (size_t)(sp * 2) * 65536 + (size_t)n * 128 + p;
            v = (g_g2p[base] + g_g2p[base + 65536]) * INV256;
        }
        s_in[k * 2 + r] = v;
    }
    __syncthreads();

    int cpair = tid & 127;
    int rhalf = tid >> 7;          // row r0 + rhalf

    // 4-deep staging: wb[p] holds kb = p, then rotates (kb+4)
    u32 wb[4][8];
#pragma unroll
    for (int p = 0; p < 4; p++)
#pragma unroll
        for (int i = 0; i < 8; i++) wb[p][i] = g_w1h[(p * 8 + i) * 128 + cpair];

    // two independent chains per output column
    float a0a = 0.f, a0b = 0.f, a1a = 0.f, a1b = 0.f;

#pragma unroll 4
    for (int kb = 0; kb < 64; kb++) {
        int cur = kb & 3;
#pragma unroll
        for (int i = 0; i < 8; i++) {
            float2 w = __half22float2(*(__half2*)&wb[cur][i]);
            float a = s_in[(kb * 8 + i) * 2 + rhalf];
            if (i & 1) { a0b += a * w.x; a1b += a * w.y; }
            else       { a0a += a * w.x; a1a += a * w.y; }
        }
        if (kb < 60) {
#pragma unroll
            for (int i = 0; i < 8; i++)
                wb[cur][i] = g_w1h[((kb + 4) * 8 + i) * 128 + cpair];
        }
    }
    float acc0 = a0a + a0b;
    float acc1 = a1a + a1b;

    float gt0 = b1[cpair], gt1 = b1[cpair + 128];
#pragma unroll
    for (int q = 0; q < 16; q++) {
        gt0 += g_gtp[q * 256 + cpair];
        gt1 += g_gtp[q * 256 + cpair + 128];
    }
    int row = r0 + rhalf;
    out_one[row * 256 + cpair]       = (s_in[cpair * 2 + rhalf]         + GAIN * tanh_fast((acc0 + gt0) * RSQRT2)) * RSQRT2;
    out_one[row * 256 + cpair + 128] = (s_in[(cpair + 128) * 2 + rhalf] + GAIN * tanh_fast((acc1 + gt1) * RSQRT2)) * RSQRT2;
}

// ---------------------------------------------------------------------------
// k_two helpers (128x128 tile, 256 threads, 8 warps)
// ---------------------------------------------------------------------------
__device__ __forceinline__ void mma_tile(u32 Ah, u32 Bb, float (&acc)[2][8][4]) {
#pragma unroll
    for (int mi = 0; mi < 2; mi++)
#pragma unroll
        for (int nt = 0; nt < 8; nt++)
#pragma unroll
            for (int c = 0; c < 4; c++) acc[mi][nt][c] = 0.f;
#pragma unroll
    for (int ks = 0; ks < 8; ks++) {
        u32 b[4][4], a0[4], a1[4];
#pragma unroll
        for (int nb = 0; nb < 4; nb++) ldsm4(b[nb], Bb + nb * 16 * BSTRIDE + ks * 32);
        ldsm4(a0, Ah + ks * 32);
        ldsm4(a1, Ah + 16 * BSTRIDE + ks * 32);
#pragma unroll
        for (int nb = 0; nb < 4; nb++) {
            mma16816(acc[0][nb * 2 + 0], a0, b[nb]);
            mma16816(acc[0][nb * 2 + 1], a0, b[nb] + 2);
            mma16816(acc[1][nb * 2 + 0], a1, b[nb]);
            mma16816(acc[1][nb * 2 + 1], a1, b[nb] + 2);
        }
    }
}

__device__ __forceinline__ void stage_tile(char* smem, const float* __restrict__ src,
                                           int rr, int kc) {
    float4 csum = make_float4(0.f, 0.f, 0.f, 0.f);
#pragma unroll
    for (int it = 0; it < 16; it++) {
        int row = rr + it * 8;
        float4 v = *(const float4*)(src + (size_t)it * 8 * 65536);
        csum.x += v.x; csum.y += v.y; csum.z += v.z; csum.w += v.w;
        __half2 h0 = __float22half2_rn(make_float2(v.x, v.y));
        __half2 h1 = __float22half2_rn(make_float2(v.z, v.w));
        u64 hp = (u64)(*(u32*)&h0) | ((u64)(*(u32*)&h1) << 32);
        *(u64*)(smem + S_AH + row * BSTRIDE + kc * 8) = hp;
    }
    *(float4*)(smem + S_RED + (rr * 32 + kc) * 16) = csum;
}

__device__ __forceinline__ void epi_tile(const char* smem, float (&acc)[2][8][4],
                                         const float2* bz, size_t ibase, int j,
                                         int lane, int mw, int nw,
                                         float* __restrict__ out_two) {
    int col0 = nw * 64 + (lane & 3) * 2;
#pragma unroll
    for (int mi = 0; mi < 2; mi++) {
#pragma unroll
        for (int half = 0; half < 2; half++) {
            int rt = mw * 32 + mi * 16 + half * 8 + (lane >> 2);
            float* orow = out_two + ((ibase + rt) * 512 + j) * 128;
#pragma unroll
            for (int nt = 0; nt < 8; nt++) {
                int c = col0 + nt * 8;
                __half2 hh = *(const __half2*)(smem + S_AH + rt * BSTRIDE + c * 2);
                float2 hf = __half22float2(hh);
                float d0 = acc[mi][nt][half * 2 + 0] + bz[nt].x;
                float d1 = acc[mi][nt][half * 2 + 1] + bz[nt].y;
                float2 o;
                o.x = (hf.x + GAIN * tanh_fast(d0)) * RSQRT2;
                o.y = (hf.y + GAIN * tanh_fast(d1)) * RSQRT2;
                *(float2*)(orow + c) = o;
            }
        }
    }
}

// ---------------------------------------------------------------------------
// K3: persistent fp16 mma.sync. grid NBLK+32 x 256 threads.
// bid 0..15:  gt partials (compute own g1)      — run FIRST, overlap GEMM
// bid 16..31: W1 -> packed fp16 conversion      — run FIRST, overlap GEMM
// bid 32..:   GEMM, loop t = bid-32; t < NTILE; t += NBLK. W2 staged once.
// ---------------------------------------------------------------------------
__global__ void __launch_bounds__(256, 2)
k_two(const float* __restrict__ h_two,
      const float* __restrict__ b2,
      const float* __restrict__ Wg,
      const float* __restrict__ W2,
      const float* __restrict__ W1,
      const float* __restrict__ h_one,
      float* __restrict__ out_two) {
    extern __shared__ char smem[];
    int tid = threadIdx.x;

    if (blockIdx.x < 16) {
        // ---- gt partials: block q covers k in [q*32, q*32+32); own g1 ----
        __shared__ float s_part[8][32];
        __shared__ float s_g1[32];
        int q = blockIdx.x;
        {
            int i = tid & 31;
            int chk = tid >> 5;
            int kk = q * 32 + i;
            int sP = kk >> 8;
            int col = kk & 255;
            const float* p = h_one + (size_t)(sP * 256 + chk * 32) * 256 + col;
            float sum = 0.f;
#pragma unroll 8
            for (int r = 0; r < 32; r++) sum += p[r * 256];
            s_part[chk][i] = sum;
        }
        __syncthreads();
        if (tid < 32) {
            float t = 0.f;
#pragma unroll
            for (int c8 = 0; c8 < 8; c8++) t += s_part[c8][tid];
            s_g1[tid] = t * INV256;
        }
        __syncthreads();
        int c = tid;
        float acc = 0.f;
#pragma unroll
        for (int kb = 0; kb < 4; kb++) {
            float w[8];
#pragma unroll
            for (int i = 0; i < 8; i++) w[i] = Wg[(q * 32 + kb * 8 + i) * 256 + c];
#pragma unroll
            for (int i = 0; i < 8; i++) acc += s_g1[kb * 8 + i] * w[i];
        }
        g_gtp[q * 256 + c] = acc;
        return;
    }

    if (blockIdx.x < 32) {
        // ---- W1 conversion: block q covers k in [q*32, q*32+32) ----
        int q = blockIdx.x - 16;
        int cpair = tid & 127;
        int kh = tid >> 7;
#pragma unroll
        for (int kk = 0; kk < 16; kk++) {
            int k = q * 32 + kh * 16 + kk;
            float w0 = W1[k * 256 + cpair];
            float w1 = W1[k * 256 + cpair + 128];
            __half2 h = __float22half2_rn(make_float2(w0, w1));
            g_w1h[k * 128 + cpair] = *(u32*)&h;
        }
        return;
    }

    u32 sb = smem_u32(smem);
    int lane = tid & 31;
    int w = tid >> 5;
    int rr = tid >> 5;             // 0..7 (row group for staging)
    int kc = tid & 31;             // k-quad

    // stage W2T fp16 image ONCE per block, directly from W2 (transpose+cvt)
    {
        int n = tid & 127;
        int kh = tid >> 7;
#pragma unroll
        for (int kk = 0; kk < 32; kk++) {
            int k = kh * 64 + kk * 2;
            float w0 = W2[k * 128 + n];
            float w1 = W2[(k + 1) * 128 + n];
            __half2 h = __float22half2_rn(make_float2(w0, w1));
            *(__half2*)(smem + S_WH + n * BSTRIDE + k * 2) = h;
        }
    }

    int mw = w & 3;
    int nw = w >> 2;
    u32 a_off = (u32)((mw * 32 + (lane & 15)) * BSTRIDE + ((lane >> 4) << 4));
    u32 b_off = (u32)((((lane & 7) + ((lane >> 4) << 3)) * BSTRIDE) + (((lane >> 3) & 1) << 4));
    u32 Ah = sb + S_AH + a_off;
    u32 Bb = sb + S_WH + (u32)(nw * 64 * BSTRIDE) + b_off;

    int col0 = nw * 64 + (lane & 3) * 2;
    float2 bz[8];
#pragma unroll
    for (int nt = 0; nt < 8; nt++) bz[nt] = *(const float2*)(b2 + col0 + nt * 8);

    float acc[2][8][4];

    for (int t = blockIdx.x - 32; t < NTILE; t += NBLK) {
        int j = t & 511;
        int ch = t >> 9;
        int s = ch >> 1;
        int h = ch & 1;
        size_t ibase = (size_t)(s * 256 + h * 128);
        const float* src = h_two + (ibase + rr) * 65536 + (size_t)j * 128 + kc * 4;

        stage_tile(smem, src, rr, kc);

        // prefetch next tile's A slice into L2 (register-free)
        int tn = t + NBLK;
        if (tn < NTILE) {
            int jn = tn & 511;
            int chn = tn >> 9;
            size_t ibn = (size_t)((chn >> 1) * 256 + (chn & 1) * 128);
            const float* srcn = h_two + (ibn + rr) * 65536 + (size_t)jn * 128 + kc * 4;
#pragma unroll
            for (int it = 0; it < 16; it++) prefetch_l2(srcn + (size_t)it * 8 * 65536);
        }
        __syncthreads();

        // g2 partial for this tile
        if (tid < 128) {
            int p = tid;
            float sum = 0.f;
#pragma unroll
            for (int r8 = 0; r8 < 8; r8++)
                sum += *(const float*)(smem + S_RED + (r8 * 32 + (p >> 2)) * 16 + (p & 3) * 4);
            g_g2p[(size_t)(s * 2 + h) * 65536 + (size_t)j * 128 + p] = sum;
        }

        mma_tile(Ah, Bb, acc);
        epi_tile(smem, acc, bz, ibase, j, lane, mw, nw, out_two);
        __syncthreads();   // A buffer reused next iteration
    }
}

// ---------------------------------------------------------------------------
extern "C" void kernel_launch(void* const* d_in, const int* in_sizes, int n_in,
                              void* d_out, int out_size) {
    const float* h_one = (const float*)d_in[0];
    const float* h_two = (const float*)d_in[1];
    const float* W1    = (const float*)d_in[2];
    const float* b1    = (const float*)d_in[3];
    const float* Wg    = (const float*)d_in[4];
    const float* W2    = (const float*)d_in[5];
    const float* b2    = (const float*)d_in[6];

    float* out_one = (float*)d_out;
    float* out_two = (float*)d_out + 512 * 256;

    cudaFuncSetAttribute(k_two, cudaFuncAttributeMaxDynamicSharedMemorySize, SMEM_TWO);

    k_two<<<NBLK + 32, 256, SMEM_TWO>>>(h_two, b2, Wg, W2, W1, h_one, out_two);
    k_one<<<256, 256>>>(h_one, b1, out_one);
}